// round 11
// baseline (speedup 1.0000x reference)
#include <cuda_runtime.h>
#include <cuda_bf16.h>

#define CROP 81
#define PIX  (CROP * CROP)        // 6561
#define SPLIT 3                   // 27 rows per block
#define ROWS_PER 27
#define KPT 3                     // rows per thread per chunk
#define CHUNKS 3                  // 3 chunks of 9 rows -> 27 rows
#define THREADS 256               // 243 active (3 groups x 81 cols)

// One block = one (n,p) crop, 27 output rows (setup amortized 3x vs SPLIT=9).
// Each thread owns a fixed column j and 3 chunks of 3 consecutive rows;
// 4 image rows serve 3 output rows via register reuse.
__global__ __launch_bounds__(THREADS)
void selectnet_kernel(const float* __restrict__ img,
                      const int*   __restrict__ label,
                      const float* __restrict__ points,
                      float*       __restrict__ out,
                      int N)
{
    const int W = 512, H = 512;
    const size_t plane = (size_t)H * W;

    // x: (wx0, wx1, bits[c0 | c1<<9 | (lx+1)<<18], 0)
    // y: (wy0, wy1, bits[y0 raw unclamped], bits[lyrow or -1])
    __shared__ float4 sxt[CROP];
    __shared__ float4 syt[CROP];

    const int q = blockIdx.x;       // n*6 + p
    const int p = q % 6;
    const int n = q / 6;
    const int t = threadIdx.x;

    if (t < CROP) {
        // ---- exact replication of reference float32 op chain ----
        const float* pt = points + (size_t)n * 18;
        float py, px;
        if (p < 5) {
            py = pt[(p + 1) * 2 + 0];
            px = pt[(p + 1) * 2 + 1];
        } else {
            py = __fdiv_rn(__fadd_rn(__fadd_rn(pt[12], pt[14]), pt[16]), 3.0f);
            px = __fdiv_rn(__fadd_rn(__fadd_rn(pt[13], pt[15]), pt[17]), 3.0f);
        }
        const float fw = 511.0f, fh = 511.0f;
        const float sx = (float)(80.0 / 511.0);   // (CROP-1)/(W-1)
        const float sy = (float)(80.0 / 512.0);   // (CROP-1)/H  (reference asymmetry)
        const float delta = __fdiv_rn(2.0f, 80.0f);

        float tx = __fadd_rn(-1.0f, __fdiv_rn(__fmul_rn(2.0f, px), fw));
        float ty = __fadd_rn(-1.0f, __fdiv_rn(__fmul_rn(2.0f, py), fh));
        float base = __fadd_rn(-1.0f, __fmul_rn((float)t, delta));
        float gx = __fadd_rn(__fmul_rn(sx, base), tx);
        float gy = __fadd_rn(__fmul_rn(sy, base), ty);
        float ix = __fmul_rn(__fmul_rn(__fadd_rn(gx, 1.0f), 0.5f), fw);
        float iy = __fmul_rn(__fmul_rn(__fadd_rn(gy, 1.0f), 0.5f), fh);

        // x table (index = j)
        float x0f = floorf(ix);
        float wx1v = ix - x0f;
        int x0 = (int)x0f, x1 = x0 + 1;
        float wx0 = (x0 >= 0 && x0 <= W - 1) ? (1.0f - wx1v) : 0.0f;
        float wx1 = (x1 >= 0 && x1 <= W - 1) ? wx1v : 0.0f;
        int c0 = min(max(x0, 0), W - 1);
        int c1 = min(max(x1, 0), W - 1);
        float xr = rintf(ix);
        int lx = (xr >= 0.0f && xr <= fw) ? (int)xr : -1;
        sxt[t] = make_float4(wx0, wx1,
                             __int_as_float(c0 | (c1 << 9) | ((lx + 1) << 18)), 0.0f);

        // y table (index = i): keep y0 UNCLAMPED (row base for tap reuse)
        float y0f = floorf(iy);
        float wy1v = iy - y0f;
        int y0 = (int)y0f, y1 = y0 + 1;
        float wy0 = (y0 >= 0 && y0 <= H - 1) ? (1.0f - wy1v) : 0.0f;
        float wy1 = (y1 >= 0 && y1 <= H - 1) ? wy1v : 0.0f;
        float yr = rintf(iy);
        int lyrow = (yr >= 0.0f && yr <= fh) ? ((int)yr) * W : -1;
        syt[t] = make_float4(wy0, wy1, __int_as_float(y0), __int_as_float(lyrow));
    }
    __syncthreads();

    if (t >= 3 * CROP) return;
    const int g = t / CROP;            // 0..2
    const int j = t - g * CROP;        // 0..80
    const int rbase = blockIdx.y * ROWS_PER + g * KPT;   // chunk ck adds ck*9

    // hoisted x-side state (constant across chunks)
    float4 xt = sxt[j];
    int xp = __float_as_int(xt.z);
    const int c0 = xp & 511, c1 = (xp >> 9) & 511, lx = (xp >> 18) - 1;

    const float* imgn = img   + (size_t)n * 3 * plane;
    const int*   labn = label + (size_t)n * plane;
    float*       outq  = out + (size_t)q * 3 * PIX + j;
    float*       predq = out + (size_t)N * 6 * 3 * PIX + (size_t)q * PIX + j;
    const int target = p + 1;

    #pragma unroll
    for (int ck = 0; ck < CHUNKS; ++ck) {
        const int i0 = rbase + ck * (KPT * 3);   // 9-row stride between chunks

        float4 yt0 = syt[i0], yt1 = syt[i0 + 1], yt2 = syt[i0 + 2];
        int y0r = __float_as_int(yt0.z);
        // rr0(k) = y0raw(k) - y0raw(0) is exactly k or k-1 (y-step = 0.99805 px)
        bool p1 = (__float_as_int(yt1.z) - y0r) == 1;
        bool p2 = (__float_as_int(yt2.z) - y0r) == 2;
        int lyr0 = __float_as_int(yt0.w);
        int lyr1 = __float_as_int(yt1.w);
        int lyr2 = __float_as_int(yt2.w);

        // 4 load rows (clamped); where clip differs from reference, weight = 0
        int ro0 = min(max(y0r + 0, 0), H - 1) << 9;
        int ro1 = min(max(y0r + 1, 0), H - 1) << 9;
        int ro2 = min(max(y0r + 2, 0), H - 1) << 9;
        int ro3 = min(max(y0r + 3, 0), H - 1) << 9;

        // ---- label taps (batched) ----
        int la0 = ((lx | lyr0) >= 0) ? __ldg(labn + lyr0 + lx) : 0;
        int la1 = ((lx | lyr1) >= 0) ? __ldg(labn + lyr1 + lx) : 0;
        int la2 = ((lx | lyr2) >= 0) ? __ldg(labn + lyr2 + lx) : 0;

        // ---- image: 4-row taps per channel, vertical reuse via selects ----
        #pragma unroll
        for (int c = 0; c < 3; ++c) {
            const float* cp = imgn + (size_t)c * plane;
            float a0 = __ldg(cp + ro0 + c0), b0 = __ldg(cp + ro0 + c1);
            float a1 = __ldg(cp + ro1 + c0), b1 = __ldg(cp + ro1 + c1);
            float a2 = __ldg(cp + ro2 + c0), b2 = __ldg(cp + ro2 + c1);
            float a3 = __ldg(cp + ro3 + c0), b3 = __ldg(cp + ro3 + c1);

            float hl0 = a0 * xt.x + b0 * xt.y;
            float hl1 = a1 * xt.x + b1 * xt.y;
            float hl2 = a2 * xt.x + b2 * xt.y;
            float hl3 = a3 * xt.x + b3 * xt.y;

            float o0 = hl0 * yt0.x + hl1 * yt0.y;                   // k=0: rr0=0 always
            float h10 = p1 ? hl1 : hl0, h11 = p1 ? hl2 : hl1;
            float o1 = h10 * yt1.x + h11 * yt1.y;
            float h20 = p2 ? hl2 : hl1, h21 = p2 ? hl3 : hl2;
            float o2 = h20 * yt2.x + h21 * yt2.y;

            float* op = outq + (size_t)c * PIX + (size_t)i0 * CROP;
            op[0 * CROP] = o0;
            op[1 * CROP] = o1;
            op[2 * CROP] = o2;
        }

        // ---- preds ----
        float pr0, pr1, pr2;
        if (p < 5) {
            pr0 = (la0 == target) ? 1.0f : 0.0f;
            pr1 = (la1 == target) ? 1.0f : 0.0f;
            pr2 = (la2 == target) ? 1.0f : 0.0f;
        } else {
            pr0 = (la0 == 6) ? 1.0f : (la0 == 7) ? 2.0f : (la0 == 8) ? 3.0f : 0.0f;
            pr1 = (la1 == 6) ? 1.0f : (la1 == 7) ? 2.0f : (la1 == 8) ? 3.0f : 0.0f;
            pr2 = (la2 == 6) ? 1.0f : (la2 == 7) ? 2.0f : (la2 == 8) ? 3.0f : 0.0f;
        }
        float* pp = predq + (size_t)i0 * CROP;
        pp[0 * CROP] = pr0;
        pp[1 * CROP] = pr1;
        pp[2 * CROP] = pr2;
    }
}

extern "C" void kernel_launch(void* const* d_in, const int* in_sizes, int n_in,
                              void* d_out, int out_size) {
    const float* img    = (const float*)d_in[0];   // (N, 3, 512, 512) f32
    const int*   label  = (const int*)  d_in[1];   // (N, 512, 512) i32
    const float* points = (const float*)d_in[2];   // (N, 9, 2) f32
    float* out = (float*)d_out;

    int N = in_sizes[2] / 18;                      // points = N*9*2

    dim3 grid(N * 6, SPLIT);
    selectnet_kernel<<<grid, THREADS>>>(img, label, points, out, N);
}

// round 12
// speedup vs baseline: 1.1364x; 1.1364x over previous
#include <cuda_runtime.h>
#include <cuda_bf16.h>

#define CROP 81
#define PIX  (CROP * CROP)        // 6561
#define SPLIT 3                   // 27 rows per block
#define THREADS 256               // 243 active (3 groups x 81 cols)

// One block = one (n,p) crop, 27 output rows. Each thread owns a fixed
// column j and 9 consecutive rows, processed as 3 chunks of 3 with the two
// boundary horizontal-lerp values carried in registers: 10 image rows serve
// 9 output rows (20 taps/ch per 9 px = 6.67 loads/px vs 8).
__global__ __launch_bounds__(THREADS)
void selectnet_kernel(const float* __restrict__ img,
                      const int*   __restrict__ label,
                      const float* __restrict__ points,
                      float*       __restrict__ out,
                      int N)
{
    const int W = 512, H = 512;
    const size_t plane = (size_t)H * W;

    // x: (wx0, wx1, bits[c0 | c1<<9 | (lx+1)<<18], 0)
    // y: (wy0, wy1, bits[y0 raw unclamped], bits[lyrow or -1])
    __shared__ float4 sxt[CROP];
    __shared__ float4 syt[CROP];

    const int q = blockIdx.x;       // n*6 + p
    const int p = q % 6;
    const int n = q / 6;
    const int t = threadIdx.x;

    if (t < CROP) {
        // ---- exact replication of reference float32 op chain ----
        const float* pt = points + (size_t)n * 18;
        float py, px;
        if (p < 5) {
            py = pt[(p + 1) * 2 + 0];
            px = pt[(p + 1) * 2 + 1];
        } else {
            py = __fdiv_rn(__fadd_rn(__fadd_rn(pt[12], pt[14]), pt[16]), 3.0f);
            px = __fdiv_rn(__fadd_rn(__fadd_rn(pt[13], pt[15]), pt[17]), 3.0f);
        }
        const float fw = 511.0f, fh = 511.0f;
        const float sx = (float)(80.0 / 511.0);   // (CROP-1)/(W-1)
        const float sy = (float)(80.0 / 512.0);   // (CROP-1)/H  (reference asymmetry)
        const float delta = __fdiv_rn(2.0f, 80.0f);

        float tx = __fadd_rn(-1.0f, __fdiv_rn(__fmul_rn(2.0f, px), fw));
        float ty = __fadd_rn(-1.0f, __fdiv_rn(__fmul_rn(2.0f, py), fh));
        float base = __fadd_rn(-1.0f, __fmul_rn((float)t, delta));
        float gx = __fadd_rn(__fmul_rn(sx, base), tx);
        float gy = __fadd_rn(__fmul_rn(sy, base), ty);
        float ix = __fmul_rn(__fmul_rn(__fadd_rn(gx, 1.0f), 0.5f), fw);
        float iy = __fmul_rn(__fmul_rn(__fadd_rn(gy, 1.0f), 0.5f), fh);

        // x table (index = j)
        float x0f = floorf(ix);
        float wx1v = ix - x0f;
        int x0 = (int)x0f, x1 = x0 + 1;
        float wx0 = (x0 >= 0 && x0 <= W - 1) ? (1.0f - wx1v) : 0.0f;
        float wx1 = (x1 >= 0 && x1 <= W - 1) ? wx1v : 0.0f;
        int c0 = min(max(x0, 0), W - 1);
        int c1 = min(max(x1, 0), W - 1);
        float xr = rintf(ix);
        int lx = (xr >= 0.0f && xr <= fw) ? (int)xr : -1;
        sxt[t] = make_float4(wx0, wx1,
                             __int_as_float(c0 | (c1 << 9) | ((lx + 1) << 18)), 0.0f);

        // y table (index = i): keep y0 UNCLAMPED (row base for tap reuse)
        float y0f = floorf(iy);
        float wy1v = iy - y0f;
        int y0 = (int)y0f, y1 = y0 + 1;
        float wy0 = (y0 >= 0 && y0 <= H - 1) ? (1.0f - wy1v) : 0.0f;
        float wy1 = (y1 >= 0 && y1 <= H - 1) ? wy1v : 0.0f;
        float yr = rintf(iy);
        int lyrow = (yr >= 0.0f && yr <= fh) ? ((int)yr) * W : -1;
        syt[t] = make_float4(wy0, wy1, __int_as_float(y0), __int_as_float(lyrow));
    }
    __syncthreads();

    if (t >= 3 * CROP) return;
    const int g = t / CROP;            // 0..2
    const int j = t - g * CROP;        // 0..80
    const int i0 = blockIdx.y * 27 + g * 9;

    float4 xt = sxt[j];
    int xp = __float_as_int(xt.z);
    const int c0 = xp & 511, c1 = (xp >> 9) & 511, lx = (xp >> 18) - 1;

    const float* imgn = img   + (size_t)n * 3 * plane;
    const int*   labn = label + (size_t)n * plane;
    float*       outq  = out + (size_t)q * 3 * PIX + (size_t)i0 * CROP + j;
    float*       predq = out + (size_t)N * 6 * 3 * PIX + (size_t)q * PIX + (size_t)i0 * CROP + j;
    const int target = p + 1;

    const int base0 = __float_as_int(syt[i0].z);   // raw y0 of first row

    float hp2[3], hp1[3];   // per-channel carries: hl[3m-1], hl[3m]

    // ================= chunk 0 (rows k = 0..2, window rows 0..3) =================
    {
        float4 ya = syt[i0], yb = syt[i0 + 1], yc = syt[i0 + 2];
        bool pb = (__float_as_int(yb.z) - base0) == 1;
        bool pc = (__float_as_int(yc.z) - base0) == 2;
        int lyr0 = __float_as_int(ya.w);
        int lyr1 = __float_as_int(yb.w);
        int lyr2 = __float_as_int(yc.w);

        int ro0 = min(max(base0 + 0, 0), H - 1) << 9;
        int ro1 = min(max(base0 + 1, 0), H - 1) << 9;
        int ro2 = min(max(base0 + 2, 0), H - 1) << 9;
        int ro3 = min(max(base0 + 3, 0), H - 1) << 9;

        int la0 = ((lx | lyr0) >= 0) ? __ldg(labn + lyr0 + lx) : 0;
        int la1 = ((lx | lyr1) >= 0) ? __ldg(labn + lyr1 + lx) : 0;
        int la2 = ((lx | lyr2) >= 0) ? __ldg(labn + lyr2 + lx) : 0;

        #pragma unroll
        for (int c = 0; c < 3; ++c) {
            const float* cp = imgn + (size_t)c * plane;
            float a0 = __ldg(cp + ro0 + c0), b0 = __ldg(cp + ro0 + c1);
            float a1 = __ldg(cp + ro1 + c0), b1 = __ldg(cp + ro1 + c1);
            float a2 = __ldg(cp + ro2 + c0), b2 = __ldg(cp + ro2 + c1);
            float a3 = __ldg(cp + ro3 + c0), b3 = __ldg(cp + ro3 + c1);

            float h0 = a0 * xt.x + b0 * xt.y;
            float h1 = a1 * xt.x + b1 * xt.y;
            float h2 = a2 * xt.x + b2 * xt.y;
            float h3 = a3 * xt.x + b3 * xt.y;

            float o0 = h0 * ya.x + h1 * ya.y;
            float o1 = (pb ? h1 : h0) * yb.x + (pb ? h2 : h1) * yb.y;
            float o2 = (pc ? h2 : h1) * yc.x + (pc ? h3 : h2) * yc.y;

            float* op = outq + (size_t)c * PIX;
            __stcs(op + 0 * CROP, o0);
            __stcs(op + 1 * CROP, o1);
            __stcs(op + 2 * CROP, o2);

            hp2[c] = h2; hp1[c] = h3;
        }

        float pr0, pr1, pr2;
        if (p < 5) {
            pr0 = (la0 == target) ? 1.0f : 0.0f;
            pr1 = (la1 == target) ? 1.0f : 0.0f;
            pr2 = (la2 == target) ? 1.0f : 0.0f;
        } else {
            pr0 = (la0 == 6) ? 1.0f : (la0 == 7) ? 2.0f : (la0 == 8) ? 3.0f : 0.0f;
            pr1 = (la1 == 6) ? 1.0f : (la1 == 7) ? 2.0f : (la1 == 8) ? 3.0f : 0.0f;
            pr2 = (la2 == 6) ? 1.0f : (la2 == 7) ? 2.0f : (la2 == 8) ? 3.0f : 0.0f;
        }
        __stcs(predq + 0 * CROP, pr0);
        __stcs(predq + 1 * CROP, pr1);
        __stcs(predq + 2 * CROP, pr2);
    }

    // ================= chunks m = 1,2 (rows 3m..3m+2, new window rows 3m+1..3m+3) ==
    #pragma unroll
    for (int m = 1; m < 3; ++m) {
        const int k0 = 3 * m;
        float4 ya = syt[i0 + k0], yb = syt[i0 + k0 + 1], yc = syt[i0 + k0 + 2];
        bool pa = (__float_as_int(ya.z) - base0) == k0;
        bool pb = (__float_as_int(yb.z) - base0) == k0 + 1;
        bool pc = (__float_as_int(yc.z) - base0) == k0 + 2;
        int lyr0 = __float_as_int(ya.w);
        int lyr1 = __float_as_int(yb.w);
        int lyr2 = __float_as_int(yc.w);

        int roA = min(max(base0 + k0 + 1, 0), H - 1) << 9;
        int roB = min(max(base0 + k0 + 2, 0), H - 1) << 9;
        int roC = min(max(base0 + k0 + 3, 0), H - 1) << 9;

        int la0 = ((lx | lyr0) >= 0) ? __ldg(labn + lyr0 + lx) : 0;
        int la1 = ((lx | lyr1) >= 0) ? __ldg(labn + lyr1 + lx) : 0;
        int la2 = ((lx | lyr2) >= 0) ? __ldg(labn + lyr2 + lx) : 0;

        #pragma unroll
        for (int c = 0; c < 3; ++c) {
            const float* cp = imgn + (size_t)c * plane;
            float aA = __ldg(cp + roA + c0), bA = __ldg(cp + roA + c1);
            float aB = __ldg(cp + roB + c0), bB = __ldg(cp + roB + c1);
            float aC = __ldg(cp + roC + c0), bC = __ldg(cp + roC + c1);

            float h1 = aA * xt.x + bA * xt.y;   // hl[k0+1]
            float h2 = aB * xt.x + bB * xt.y;   // hl[k0+2]
            float h3 = aC * xt.x + bC * xt.y;   // hl[k0+3]
            float hm1 = hp1[c];                 // hl[k0]
            float hm2 = hp2[c];                 // hl[k0-1]

            float o0 = (pa ? hm1 : hm2) * ya.x + (pa ? h1 : hm1) * ya.y;
            float o1 = (pb ? h1 : hm1) * yb.x + (pb ? h2 : h1) * yb.y;
            float o2 = (pc ? h2 : h1) * yc.x + (pc ? h3 : h2) * yc.y;

            float* op = outq + (size_t)c * PIX + (size_t)k0 * CROP;
            __stcs(op + 0 * CROP, o0);
            __stcs(op + 1 * CROP, o1);
            __stcs(op + 2 * CROP, o2);

            hp2[c] = h2; hp1[c] = h3;
        }

        float pr0, pr1, pr2;
        if (p < 5) {
            pr0 = (la0 == target) ? 1.0f : 0.0f;
            pr1 = (la1 == target) ? 1.0f : 0.0f;
            pr2 = (la2 == target) ? 1.0f : 0.0f;
        } else {
            pr0 = (la0 == 6) ? 1.0f : (la0 == 7) ? 2.0f : (la0 == 8) ? 3.0f : 0.0f;
            pr1 = (la1 == 6) ? 1.0f : (la1 == 7) ? 2.0f : (la1 == 8) ? 3.0f : 0.0f;
            pr2 = (la2 == 6) ? 1.0f : (la2 == 7) ? 2.0f : (la2 == 8) ? 3.0f : 0.0f;
        }
        float* pp = predq + (size_t)k0 * CROP;
        __stcs(pp + 0 * CROP, pr0);
        __stcs(pp + 1 * CROP, pr1);
        __stcs(pp + 2 * CROP, pr2);
    }
}

extern "C" void kernel_launch(void* const* d_in, const int* in_sizes, int n_in,
                              void* d_out, int out_size) {
    const float* img    = (const float*)d_in[0];   // (N, 3, 512, 512) f32
    const int*   label  = (const int*)  d_in[1];   // (N, 512, 512) i32
    const float* points = (const float*)d_in[2];   // (N, 9, 2) f32
    float* out = (float*)d_out;

    int N = in_sizes[2] / 18;                      // points = N*9*2

    dim3 grid(N * 6, SPLIT);
    selectnet_kernel<<<grid, THREADS>>>(img, label, points, out, N);
}